// round 4
// baseline (speedup 1.0000x reference)
#include <cuda_runtime.h>
#include <stdint.h>

#define NB_COUNT 32
#define DIM 128                 // floats per row
#define ROW_BYTES (DIM * 4)     // 512 B

// 256-bit pinned gather: sm_103a requires .v8.b32 / .v4.b64 with
// .L2::evict_last. Loads 8 consecutive f32 (32 B).
__device__ __forceinline__ void ld_row_pin8(const char* p, float* a) {
    unsigned r0, r1, r2, r3, r4, r5, r6, r7;
    asm("ld.global.nc.L2::evict_last.v8.b32 {%0,%1,%2,%3,%4,%5,%6,%7}, [%8];"
        : "=r"(r0), "=r"(r1), "=r"(r2), "=r"(r3),
          "=r"(r4), "=r"(r5), "=r"(r6), "=r"(r7)
        : "l"(p));
    a[0] = __uint_as_float(r0); a[1] = __uint_as_float(r1);
    a[2] = __uint_as_float(r2); a[3] = __uint_as_float(r3);
    a[4] = __uint_as_float(r4); a[5] = __uint_as_float(r5);
    a[6] = __uint_as_float(r6); a[7] = __uint_as_float(r7);
}

// Index load: streaming (touched once per launch).
__device__ __forceinline__ int ld_idx_stream(const int* p) {
    int v;
    asm("ld.global.cs.s32 %0, [%1];" : "=r"(v) : "l"(p));
    return v;
}

// Output store: streaming — written once, must not evict table from L2.
__device__ __forceinline__ void st_out_stream(char* p, float4 v) {
    asm volatile("st.global.cs.v4.f32 [%0], {%1,%2,%3,%4};"
                 :: "l"(p), "f"(v.x), "f"(v.y), "f"(v.z), "f"(v.w));
}

// One warp per node. Lane owns a 32B chunk: chunk = lane & 15.
// Half-warp 0 gathers neighbor 2j, half-warp 1 gathers neighbor 2j+1
// -> two full rows (1024B coalesced) per iteration.
__global__ __launch_bounds__(256) void sum_agg_kernel(
    const int* __restrict__ neighs,
    const char* __restrict__ emb,    // [num_ids][512B]
    char* __restrict__ out,          // [node_count][512B]
    int node_count)
{
    const int warp = (blockIdx.x * blockDim.x + threadIdx.x) >> 5;
    const int lane = threadIdx.x & 31;
    if (warp >= node_count) return;

    const int chunk = lane & 15;     // which 32B chunk of the row
    const int half  = lane >> 4;     // 0 or 1: which neighbor of the pair

    // Coalesced index load: lane l gets neighbor l of this node.
    const int my_idx = ld_idx_stream(&neighs[(size_t)warp * NB_COUNT + lane]);

    float acc[8];
    #pragma unroll
    for (int i = 0; i < 8; ++i) acc[i] = 0.f;

    #pragma unroll
    for (int j = 0; j < 16; ++j) {
        const int r = __shfl_sync(0xffffffffu, my_idx, 2 * j + half);
        float v[8];
        ld_row_pin8(emb + (size_t)r * ROW_BYTES + chunk * 32, v);
        #pragma unroll
        for (int i = 0; i < 8; ++i) acc[i] += v[i];
    }

    // Merge the two half-warp partials (lane <-> lane^16 hold the same chunk).
    #pragma unroll
    for (int i = 0; i < 8; ++i)
        acc[i] += __shfl_xor_sync(0xffffffffu, acc[i], 16);

    // Store: lane half 0 writes first 16B of its chunk, half 1 the second 16B.
    float4 r4;
    if (half == 0) { r4 = make_float4(acc[0], acc[1], acc[2], acc[3]); }
    else           { r4 = make_float4(acc[4], acc[5], acc[6], acc[7]); }
    st_out_stream(out + (size_t)warp * ROW_BYTES + chunk * 32 + half * 16, r4);
}

extern "C" void kernel_launch(void* const* d_in, const int* in_sizes, int n_in,
                              void* d_out, int out_size)
{
    // metadata order: neighs (int32), node_count (int scalar), emb_table (f32)
    const int* neighs = (const int*)d_in[0];
    const char* emb = (const char*)d_in[2];
    char* out = (char*)d_out;

    const int node_count = out_size / DIM;   // out is [node_count, 128] f32

    const int threads = 256;                  // 8 warps = 8 nodes per block
    const int blocks = (node_count * 32 + threads - 1) / threads;

    sum_agg_kernel<<<blocks, threads>>>(neighs, emb, out, node_count);
}

// round 5
// speedup vs baseline: 1.0056x; 1.0056x over previous
#include <cuda_runtime.h>
#include <stdint.h>

#define NB_COUNT 32
#define DIM 128          // floats per row

// One warp per node. Lane l owns columns {l, l+32, l+64, l+96}.
// Each 128B line of a row is fetched by its own scalar LDG.32 instruction
// (32 lanes x 4B = one line), so the L1tex sees one wavefront per LDG
// (cross-LDG rate 1.0 cyc/wf) instead of 4 within-LDG replays at 2.07.
__global__ __launch_bounds__(256) void sum_agg_kernel(
    const int* __restrict__ neighs,
    const float* __restrict__ emb,   // [num_ids][128]
    float* __restrict__ out,         // [node_count][128]
    int node_count)
{
    const int warp = (blockIdx.x * blockDim.x + threadIdx.x) >> 5;
    const int lane = threadIdx.x & 31;
    if (warp >= node_count) return;

    // Coalesced index load: lane l gets neighbor l of this node.
    const int my_idx = neighs[(size_t)warp * NB_COUNT + lane];

    float a0 = 0.f, a1 = 0.f, a2 = 0.f, a3 = 0.f;

    #pragma unroll
    for (int j = 0; j < NB_COUNT; ++j) {
        const int r = __shfl_sync(0xffffffffu, my_idx, j);
        const float* row = emb + (size_t)r * DIM + lane;
        // 4 independent scalar loads = 4 separate LDG instructions,
        // each exactly one 128B line.
        const float v0 = __ldg(row);
        const float v1 = __ldg(row + 32);
        const float v2 = __ldg(row + 64);
        const float v3 = __ldg(row + 96);
        a0 += v0; a1 += v1; a2 += v2; a3 += v3;
    }

    float* o = out + (size_t)warp * DIM + lane;
    o[0]  = a0;
    o[32] = a1;
    o[64] = a2;
    o[96] = a3;
}

extern "C" void kernel_launch(void* const* d_in, const int* in_sizes, int n_in,
                              void* d_out, int out_size)
{
    // metadata order: neighs (int32), node_count (int scalar), emb_table (f32)
    const int* neighs = (const int*)d_in[0];
    const float* emb = (const float*)d_in[2];
    float* out = (float*)d_out;

    const int node_count = out_size / DIM;   // out is [node_count, 128] f32

    const int threads = 256;                  // 8 warps = 8 nodes per block
    const int blocks = (node_count * 32 + threads - 1) / threads;

    sum_agg_kernel<<<blocks, threads>>>(neighs, emb, out, node_count);
}